// round 5
// baseline (speedup 1.0000x reference)
#include <cuda_runtime.h>

#define N_PATHS   8
#define N_FEAT    128
#define CART      3
#define N_SPECIES 10
#define ROW_F4    1024u         // 4096 floats per x row = 1024 float4
#define OUT_F4    96u           // 384 floats per out row = 96 float4
#define TPB       256
#define MAX_ATOMS 1000000

__device__ int g_species[MAX_ATOMS];   // scratch: species id per atom

__global__ void species_kernel(const float* __restrict__ y, int n_atoms)
{
    int a = blockIdx.x * blockDim.x + threadIdx.x;
    if (a >= n_atoms) return;
    const float* yrow = y + (size_t)a * N_SPECIES;
    int s = 0;
    #pragma unroll
    for (int k = 1; k < N_SPECIES; ++k)
        s = (yrow[k] > 0.5f) ? k : s;
    g_species[a] = s;
}

__global__ __launch_bounds__(TPB, 8)
void wps_kernel(const float4* __restrict__ x,
                const float*  __restrict__ w,
                float4* __restrict__ out,
                unsigned total_f4,      // n_atoms * 96
                unsigned chunk)         // f4 elements per CTA (multiple of TPB)
{
    unsigned g0   = blockIdx.x * chunk;
    unsigned gend = g0 + chunk;
    if (gend > total_f4) gend = total_f4;

    for (unsigned g = g0 + threadIdx.x; g < gend; g += TPB) {
        const unsigned a    = g / OUT_F4;          // 32-bit magic-mul division
        const unsigned lane = g - a * OUT_F4;      // 0..95

        // 4 output elements e = 4*lane .. 4*lane+3 span exactly 2 features
        const unsigned e0 = lane * 4u;
        const unsigned f0 = e0 / CART;
        const unsigned r  = e0 - f0 * CART;        // e0 % 3

        const int s = __ldg(&g_species[a]);

        const float*  wsp  = w + s * (N_PATHS * N_FEAT) + f0;  // 40 KB, L1-resident
        const float4* xrow = x + (size_t)a * ROW_F4;

        float4 acc = {0.f, 0.f, 0.f, 0.f};
        #pragma unroll
        for (int p = 0; p < N_PATHS; ++p) {
            float4 xv = __ldcs(&xrow[p * OUT_F4 + lane]);   // streaming read-once
            float wa = __ldg(&wsp[p * N_FEAT]);
            float wb = __ldg(&wsp[p * N_FEAT + 1]);
            // component-to-feature map, fixed per thread by r:
            //   r=0: (wa,wa,wa,wb)  r=1: (wa,wa,wb,wb)  r=2: (wa,wb,wb,wb)
            float wy = (r == 2u) ? wb : wa;
            float wz = (r == 0u) ? wa : wb;
            acc.x = fmaf(xv.x, wa, acc.x);
            acc.y = fmaf(xv.y, wy, acc.y);
            acc.z = fmaf(xv.z, wz, acc.z);
            acc.w = fmaf(xv.w, wb, acc.w);
        }

        __stcs(&out[g], acc);   // contiguous warp store
    }
}

extern "C" void kernel_launch(void* const* d_in, const int* in_sizes, int n_in,
                              void* d_out, int out_size)
{
    const float4* x = (const float4*)d_in[0];   // [N, 4096] fp32
    const float*  y = (const float*) d_in[1];   // [N, 10] one-hot
    const float*  w = (const float*) d_in[2];   // [10, 8, 128] fp32
    float4* out = (float4*)d_out;               // [N, 384] fp32

    const int n_atoms = in_sizes[0] / 4096;

    // prologue: species per atom (tiny)
    species_kernel<<<(n_atoms + 255) / 256, 256>>>(y, n_atoms);

    const unsigned total_f4 = (unsigned)n_atoms * OUT_F4;   // 9.6M < 2^31

    int grid = 148 * 8;   // 8 CTAs/SM
    // contiguous chunk per CTA, rounded up to a multiple of TPB
    unsigned chunk = (total_f4 + grid - 1) / grid;
    chunk = (chunk + TPB - 1) / TPB * TPB;
    // shrink grid if chunking over-covers
    grid = (int)((total_f4 + chunk - 1) / chunk);

    wps_kernel<<<grid, TPB>>>(x, w, out, total_f4, chunk);
}

// round 6
// speedup vs baseline: 1.0320x; 1.0320x over previous
#include <cuda_runtime.h>

#define N_PATHS   8
#define N_FEAT    128
#define CART      3
#define N_SPECIES 10
#define ROW_F4    1024          // 4096 floats per x row = 1024 float4
#define OUT_F4    96            // 384 floats per out row = 96 float4
#define TPB       384
#define SLOTS     4             // atoms per CTA per iteration
#define LPA       96            // lanes per atom (3 full warps per atom)

__global__ __launch_bounds__(TPB, 5)
void wps_kernel(const float4* __restrict__ x,
                const float*  __restrict__ y,
                const float*  __restrict__ w,
                float4* __restrict__ out,
                int n_atoms)
{
    const int slot = threadIdx.x / LPA;    // 0..3 : which atom in the group
    const int lane = threadIdx.x % LPA;    // 0..95: which float4 of the output
    const int wl   = threadIdx.x & 31;     // lane within warp

    // the 4 output elements e = 4*lane .. 4*lane+3 span exactly 2 features
    const int e0 = lane * 4;
    const int f0 = e0 / CART;              // first feature
    const int r  = e0 - f0 * CART;         // e0 % 3, fixed per thread

    const int stride_atoms = gridDim.x * SLOTS;

    for (int a = blockIdx.x * SLOTS + slot; a < n_atoms; a += stride_atoms) {
        // ---- species via warp ballot: each warp lies entirely in one atom ----
        const float* yrow = y + (size_t)a * N_SPECIES;
        float yv = (wl < N_SPECIES) ? __ldg(&yrow[wl]) : 0.0f;
        unsigned m = __ballot_sync(0xffffffffu, yv > 0.5f);
        const int s = __ffs(m) - 1;        // exactly one bit set among lanes 0..9

        const float*  wsp  = w + s * (N_PATHS * N_FEAT) + f0;  // 40 KB, L1-resident
        const float4* xrow = x + (size_t)a * ROW_F4;

        float4 acc = {0.f, 0.f, 0.f, 0.f};
        #pragma unroll
        for (int p = 0; p < N_PATHS; ++p) {
            float4 xv = __ldcs(&xrow[p * LPA + lane]);   // streaming read-once
            float wa = __ldg(&wsp[p * N_FEAT]);
            float wb = __ldg(&wsp[p * N_FEAT + 1]);
            // component-to-feature map, fixed per thread by r:
            //   r=0: (wa,wa,wa,wb)  r=1: (wa,wa,wb,wb)  r=2: (wa,wb,wb,wb)
            float wy = (r == 2) ? wb : wa;
            float wz = (r == 0) ? wa : wb;
            acc.x = fmaf(xv.x, wa, acc.x);
            acc.y = fmaf(xv.y, wy, acc.y);
            acc.z = fmaf(xv.z, wz, acc.z);
            acc.w = fmaf(xv.w, wb, acc.w);
        }

        __stcs(&out[(size_t)a * OUT_F4 + lane], acc);
    }
}

extern "C" void kernel_launch(void* const* d_in, const int* in_sizes, int n_in,
                              void* d_out, int out_size)
{
    const float4* x = (const float4*)d_in[0];   // [N, 4096] fp32
    const float*  y = (const float*) d_in[1];   // [N, 10] one-hot
    const float*  w = (const float*) d_in[2];   // [10, 8, 128] fp32
    float4* out = (float4*)d_out;               // [N, 384] fp32

    const int n_atoms = in_sizes[0] / 4096;

    int grid = 148 * 5;                          // 5 CTAs/SM, persistent grid-stride
    int max_grid = (n_atoms + SLOTS - 1) / SLOTS;
    if (grid > max_grid) grid = max_grid;

    wps_kernel<<<grid, TPB>>>(x, y, w, out, n_atoms);
}